// round 15
// baseline (speedup 1.0000x reference)
#include <cuda_runtime.h>
#include <cstdint>

// out = log( sum_m sum_k D'[m,k] * y^k * b^m ) + CO_0,  y = a*a
//   D'[m,k] = C[m,k] * r_m / 4^k  (the /4 of x=a^2/4 folded into coefficients)
// All terms positive, D'[0,0]=1 so S >= 1 (single __logf, no exps).
// COMPILE-TIME pruning (verified rel_err ~3.9e-7 across rounds):
//   drop terms with D[m,k]*XMAX^k*BMAX^m < THRESH, XMAX=6.25, THRESH=1e-5.
// Heavy math in PACKED f32x2 (SASS FFMA2/FMUL2, PTX-only on Blackwell).
// R15 shape: vec8/thread = 4 packed lanes, 4 front-batched LDG.128 (MLP=4),
// 64-thread blocks -> 1024 CTAs (6.9/SM; halves last-wave CTA imbalance
// vs 512 CTAs @ 3.46/SM).

constexpr int MM = 8;
constexpr int KK = 17;

__host__ __device__ constexpr double coefd(int m, int k) {
    double c = 1.0;
    for (int j = 1; j <= k; ++j)
        c *= (3.5 + (double)j) /
             (((double)j - 0.5) * (2.0 * m + 4.0 + (double)j) * (double)j);
    return c;
}
__host__ __device__ constexpr double rcoefd(int m) {
    double r = 1.0;
    for (int j = 1; j <= m; ++j)
        r *= ((2.0 * j - 1.5) * (2.0 * j - 0.5)) /
             (4.0 * (2.0 * j + 3.0) * (2.0 * j + 4.0) * (double)j * (double)j);
    return r;
}
__host__ __device__ constexpr double powc(double b, int e) {
    double r = 1.0;
    for (int i = 0; i < e; ++i) r *= b;
    return r;
}

constexpr double XMAX = 6.25, BMAX = 0.95, THRESH = 1e-5;

__host__ __device__ constexpr bool keepT(int m, int k) {
    return coefd(m, k) * rcoefd(m) * powc(XMAX, k) * powc(BMAX, m) >= THRESH;
}
__host__ __device__ constexpr bool rowLive(int m) {
    for (int k = 0; k < KK; ++k)
        if (keepT(m, k)) return true;
    return false;
}
__host__ __device__ constexpr int maxK() {
    int mk = 1;
    for (int m = 0; m < MM; ++m)
        for (int k = 0; k < KK; ++k)
            if (keepT(m, k) && k > mk) mk = k;
    return mk;
}
constexpr int KLIM = maxK();

__host__ __device__ constexpr int maxLiveRow() {
    int r = 0;
    for (int m = 0; m < MM; ++m)
        if (rowLive(m)) r = m;
    return r;
}
constexpr int RTOP = maxLiveRow();

__host__ __device__ constexpr float toF(double v) {
    return (v < 1e-37 && v > -1e-37) ? 0.0f : (float)v;
}

#define CO0_F (-0.15195235f)

// ---- packed f32x2 primitives ----

__device__ __forceinline__ uint64_t pk2(float lo, float hi) {
    uint64_t r;
    asm("mov.b64 %0, {%1, %2};" : "=l"(r) : "f"(lo), "f"(hi));
    return r;
}
__device__ __forceinline__ void upk2(float& lo, float& hi, uint64_t v) {
    asm("mov.b64 {%0, %1}, %2;" : "=f"(lo), "=f"(hi) : "l"(v));
}
__device__ __forceinline__ uint64_t mul2(uint64_t a, uint64_t b) {
    uint64_t r;
    asm("mul.rn.f32x2 %0, %1, %2;" : "=l"(r) : "l"(a), "l"(b));
    return r;
}
__device__ __forceinline__ uint64_t fma2(uint64_t a, uint64_t b, uint64_t c) {
    uint64_t r;
    asm("fma.rn.f32x2 %0, %1, %2, %3;" : "=l"(r) : "l"(a), "l"(b), "l"(c));
    return r;
}

// ---- template-unrolled packed core, 4 independent lanes ----

constexpr int NL = 4;  // packed lanes per thread (8 scalar elements)

template <int M>
struct InitStep2 {
    __device__ static __forceinline__ void run(uint64_t (*acc)[NL]) {
        if constexpr (rowLive(M)) {
            constexpr float rv = toF(rcoefd(M));
#pragma unroll
            for (int l = 0; l < NL; ++l) acc[M][l] = pk2(rv, rv);
        }
        InitStep2<M + 1>::run(acc);
    }
};
template <> struct InitStep2<MM> {
    __device__ static __forceinline__ void run(uint64_t (*)[NL]) {}
};

template <int M, int K>
struct MStep2 {
    __device__ static __forceinline__ void run(const uint64_t* yk,
                                               uint64_t (*acc)[NL]) {
        if constexpr (keepT(M, K)) {
            // coefficient in y = a^2 units: D[m,k] / 4^k
            constexpr float cv = toF(coefd(M, K) * rcoefd(M) / powc(4.0, K));
            uint64_t cc = pk2(cv, cv);   // CSE'd across lanes by ptxas
#pragma unroll
            for (int l = 0; l < NL; ++l) acc[M][l] = fma2(yk[l], cc, acc[M][l]);
        }
        MStep2<M + 1, K>::run(yk, acc);
    }
};
template <int K> struct MStep2<MM, K> {
    __device__ static __forceinline__ void run(const uint64_t*,
                                               uint64_t (*)[NL]) {}
};

// even/odd packed power ladder per lane: cur = y^K, nxt = y^(K+1)
template <int K>
struct KStepEO2 {
    __device__ static __forceinline__ void run(const uint64_t* y2,
                                               const uint64_t* cur,
                                               const uint64_t* nxt,
                                               uint64_t (*acc)[NL]) {
        MStep2<0, K>::run(cur, acc);
        if constexpr (K + 1 <= KLIM) {
            uint64_t nn[NL];
#pragma unroll
            for (int l = 0; l < NL; ++l) nn[l] = mul2(cur[l], y2[l]);
            KStepEO2<K + 1>::run(y2, nxt, nn, acc);
        }
    }
};

// packed Horner in b over live rows (descending), per lane
template <int M>
struct HornerB2 {
    __device__ static __forceinline__ void run(const uint64_t (*acc)[NL],
                                               const uint64_t* b,
                                               uint64_t* S) {
#pragma unroll
        for (int l = 0; l < NL; ++l) S[l] = fma2(S[l], b[l], acc[M][l]);
        HornerB2<M - 1>::run(acc, b, S);
    }
};
template <> struct HornerB2<-1> {
    __device__ static __forceinline__ void run(const uint64_t (*)[NL],
                                               const uint64_t*, uint64_t*) {}
};

// Each thread handles float4 indices i and i+half (half in float4 units).
__global__ void __launch_bounds__(64)
ipe_vec8_kernel(const float4* __restrict__ a, const float4* __restrict__ b,
                float4* __restrict__ out, int half) {
    int i = blockIdx.x * blockDim.x + threadIdx.x;
    if (i >= half) return;

    // front-batched loads: MLP = 4 LDG.128
    float4 a0 = a[i];
    float4 a1 = a[i + half];
    float4 b0 = b[i];
    float4 b1 = b[i + half];

    uint64_t aP[NL], yP[NL], y2P[NL], bP[NL];
    aP[0] = pk2(a0.x, a0.y);
    aP[1] = pk2(a0.z, a0.w);
    aP[2] = pk2(a1.x, a1.y);
    aP[3] = pk2(a1.z, a1.w);
#pragma unroll
    for (int l = 0; l < NL; ++l) yP[l] = mul2(aP[l], aP[l]);   // y = a^2
#pragma unroll
    for (int l = 0; l < NL; ++l) y2P[l] = mul2(yP[l], yP[l]);
    bP[0] = pk2(b0.x, b0.y);
    bP[1] = pk2(b0.z, b0.w);
    bP[2] = pk2(b1.x, b1.y);
    bP[3] = pk2(b1.z, b1.w);

    uint64_t acc[MM][NL];
    InitStep2<0>::run(acc);
    KStepEO2<1>::run(y2P, yP, y2P, acc);

    uint64_t S[NL];
#pragma unroll
    for (int l = 0; l < NL; ++l) S[l] = acc[RTOP][l];
    HornerB2<RTOP - 1>::run(acc, bP, S);

    float s[2 * NL];
#pragma unroll
    for (int l = 0; l < NL; ++l) upk2(s[2 * l], s[2 * l + 1], S[l]);

    float4 o0, o1;
    o0.x = __logf(s[0]) + CO0_F;
    o0.y = __logf(s[1]) + CO0_F;
    o0.z = __logf(s[2]) + CO0_F;
    o0.w = __logf(s[3]) + CO0_F;
    o1.x = __logf(s[4]) + CO0_F;
    o1.y = __logf(s[5]) + CO0_F;
    o1.z = __logf(s[6]) + CO0_F;
    o1.w = __logf(s[7]) + CO0_F;
    out[i] = o0;
    out[i + half] = o1;
}

// ---- scalar fallback for any tail elements ----

template <int M>
struct InitStepS {
    __device__ static __forceinline__ void run(float* acc) {
        if constexpr (rowLive(M)) acc[M] = toF(rcoefd(M));
        InitStepS<M + 1>::run(acc);
    }
};
template <> struct InitStepS<MM> { __device__ static __forceinline__ void run(float*) {} };

template <int M, int K>
struct MStepS {
    __device__ static __forceinline__ void run(float yk, float* acc) {
        if constexpr (keepT(M, K))
            acc[M] = fmaf(yk, toF(coefd(M, K) * rcoefd(M) / powc(4.0, K)), acc[M]);
        MStepS<M + 1, K>::run(yk, acc);
    }
};
template <int K> struct MStepS<MM, K> { __device__ static __forceinline__ void run(float, float*) {} };

template <int K>
struct KStepS {
    __device__ static __forceinline__ void run(float y2, float cur, float nxt,
                                               float* acc) {
        MStepS<0, K>::run(cur, acc);
        if constexpr (K + 1 <= KLIM)
            KStepS<K + 1>::run(y2, nxt, cur * y2, acc);
    }
};

template <int M>
struct HornerS {
    __device__ static __forceinline__ void run(const float* acc, float b,
                                               float& S) {
        S = fmaf(S, b, acc[M]);
        HornerS<M - 1>::run(acc, b, S);
    }
};
template <> struct HornerS<-1> {
    __device__ static __forceinline__ void run(const float*, float, float&) {}
};

__global__ void __launch_bounds__(64)
ipe_tail_kernel(const float* __restrict__ a, const float* __restrict__ b,
                float* __restrict__ out, int start, int n) {
    int i = start + blockIdx.x * blockDim.x + threadIdx.x;
    if (i >= n) return;
    float y = a[i] * a[i];
    float acc[MM];
    InitStepS<0>::run(acc);
    float y2 = y * y;
    KStepS<1>::run(y2, y, y2, acc);
    float S = acc[RTOP];
    HornerS<RTOP - 1>::run(acc, b[i], S);
    out[i] = __logf(S) + CO0_F;
}

extern "C" void kernel_launch(void* const* d_in, const int* in_sizes, int n_in,
                              void* d_out, int out_size) {
    const float* a = (const float*)d_in[0];
    const float* b = (const float*)d_in[1];
    float* out = (float*)d_out;
    int n = in_sizes[0];
    int n8 = n / 8;           // vec8 groups
    int half = n8;            // float4 index offset between a thread's two loads
    if (n8 > 0) {
        int threads = 64;
        int blocks = (n8 + threads - 1) / threads;
        ipe_vec8_kernel<<<blocks, threads>>>((const float4*)a, (const float4*)b,
                                             (float4*)out, half);
    }
    int done = n8 * 8;
    if (n - done > 0) {
        int threads = 64;
        int blocks = (n - done + threads - 1) / threads;
        ipe_tail_kernel<<<blocks, threads>>>(a, b, out, done, n);
    }
}

// round 16
// speedup vs baseline: 1.0435x; 1.0435x over previous
#include <cuda_runtime.h>
#include <cstdint>

// out = log( sum_m sum_k D'[m,k] * y^k * b^m ) + CO_0,   y = a*a
//   D'[m,k] = C[m,k] * r_m / 4^k   (the /4 of x=a^2/4 folded into coefficients)
// All terms positive, D'[0,0]=1 so S >= 1: single log2 + FFMA, no exps.
// COMPILE-TIME pruning (verified rel_err ~3.9e-7 across rounds):
//   drop terms with D[m,k]*XMAX^k*BMAX^m < THRESH, XMAX=6.25, THRESH=1e-5.
// Heavy math in PACKED f32x2 (SASS FFMA2/FMUL2, PTX-only on Blackwell).
// R16 = R12's proven-best shape (vec4/thread = 2 packed lanes, 128-thread
// blocks, 1024 CTAs) + y-fold + log2/ffma epilogue. R12 had the best
// measured ncu kernel time (4.77us) vs vec2 (5.22) and vec8 (5.95).

constexpr int MM = 8;
constexpr int KK = 17;

__host__ __device__ constexpr double coefd(int m, int k) {
    double c = 1.0;
    for (int j = 1; j <= k; ++j)
        c *= (3.5 + (double)j) /
             (((double)j - 0.5) * (2.0 * m + 4.0 + (double)j) * (double)j);
    return c;
}
__host__ __device__ constexpr double rcoefd(int m) {
    double r = 1.0;
    for (int j = 1; j <= m; ++j)
        r *= ((2.0 * j - 1.5) * (2.0 * j - 0.5)) /
             (4.0 * (2.0 * j + 3.0) * (2.0 * j + 4.0) * (double)j * (double)j);
    return r;
}
__host__ __device__ constexpr double powc(double b, int e) {
    double r = 1.0;
    for (int i = 0; i < e; ++i) r *= b;
    return r;
}

constexpr double XMAX = 6.25, BMAX = 0.95, THRESH = 1e-5;

__host__ __device__ constexpr bool keepT(int m, int k) {
    return coefd(m, k) * rcoefd(m) * powc(XMAX, k) * powc(BMAX, m) >= THRESH;
}
__host__ __device__ constexpr bool rowLive(int m) {
    for (int k = 0; k < KK; ++k)
        if (keepT(m, k)) return true;
    return false;
}
__host__ __device__ constexpr int maxK() {
    int mk = 1;
    for (int m = 0; m < MM; ++m)
        for (int k = 0; k < KK; ++k)
            if (keepT(m, k) && k > mk) mk = k;
    return mk;
}
constexpr int KLIM = maxK();

__host__ __device__ constexpr int maxLiveRow() {
    int r = 0;
    for (int m = 0; m < MM; ++m)
        if (rowLive(m)) r = m;
    return r;
}
constexpr int RTOP = maxLiveRow();

__host__ __device__ constexpr float toF(double v) {
    return (v < 1e-37 && v > -1e-37) ? 0.0f : (float)v;
}

// CO_0 = lgamma(0.5) + lgamma(4.5) - lgamma(5)
#define CO0_F (-0.15195235f)
#define LN2_F (0.69314718f)

// ---- packed f32x2 primitives ----

__device__ __forceinline__ uint64_t pk2(float lo, float hi) {
    uint64_t r;
    asm("mov.b64 %0, {%1, %2};" : "=l"(r) : "f"(lo), "f"(hi));
    return r;
}
__device__ __forceinline__ void upk2(float& lo, float& hi, uint64_t v) {
    asm("mov.b64 {%0, %1}, %2;" : "=f"(lo), "=f"(hi) : "l"(v));
}
__device__ __forceinline__ uint64_t mul2(uint64_t a, uint64_t b) {
    uint64_t r;
    asm("mul.rn.f32x2 %0, %1, %2;" : "=l"(r) : "l"(a), "l"(b));
    return r;
}
__device__ __forceinline__ uint64_t fma2(uint64_t a, uint64_t b, uint64_t c) {
    uint64_t r;
    asm("fma.rn.f32x2 %0, %1, %2, %3;" : "=l"(r) : "l"(a), "l"(b), "l"(c));
    return r;
}

// ---- template-unrolled packed core, 2 independent lanes (A, B) ----

template <int M>
struct InitStep2 {
    __device__ static __forceinline__ void run(uint64_t* aA, uint64_t* aB) {
        if constexpr (rowLive(M)) {
            constexpr float rv = toF(rcoefd(M));
            aA[M] = pk2(rv, rv);
            aB[M] = pk2(rv, rv);
        }
        InitStep2<M + 1>::run(aA, aB);
    }
};
template <> struct InitStep2<MM> {
    __device__ static __forceinline__ void run(uint64_t*, uint64_t*) {}
};

template <int M, int K>
struct MStep2 {
    __device__ static __forceinline__ void run(uint64_t ykA, uint64_t ykB,
                                               uint64_t* aA, uint64_t* aB) {
        if constexpr (keepT(M, K)) {
            // coefficient in y = a^2 units: D[m,k] / 4^k
            constexpr float cv = toF(coefd(M, K) * rcoefd(M) / powc(4.0, K));
            uint64_t cc = pk2(cv, cv);       // CSE'd across lanes by ptxas
            aA[M] = fma2(ykA, cc, aA[M]);
            aB[M] = fma2(ykB, cc, aB[M]);
        }
        MStep2<M + 1, K>::run(ykA, ykB, aA, aB);
    }
};
template <int K> struct MStep2<MM, K> {
    __device__ static __forceinline__ void run(uint64_t, uint64_t, uint64_t*,
                                               uint64_t*) {}
};

// even/odd packed power ladder: cur = y^K, nxt = y^(K+1); step: nxt' = cur*y2
template <int K>
struct KStepEO2 {
    __device__ static __forceinline__ void run(uint64_t y2A, uint64_t y2B,
                                               uint64_t curA, uint64_t nxtA,
                                               uint64_t curB, uint64_t nxtB,
                                               uint64_t* aA, uint64_t* aB) {
        MStep2<0, K>::run(curA, curB, aA, aB);
        if constexpr (K + 1 <= KLIM)
            KStepEO2<K + 1>::run(y2A, y2B, nxtA, mul2(curA, y2A),
                                 nxtB, mul2(curB, y2B), aA, aB);
    }
};

// packed Horner in b over live rows (descending)
template <int M>
struct HornerB2 {
    __device__ static __forceinline__ void run(const uint64_t* aA,
                                               const uint64_t* aB,
                                               uint64_t bA, uint64_t bB,
                                               uint64_t& SA, uint64_t& SB) {
        SA = fma2(SA, bA, aA[M]);
        SB = fma2(SB, bB, aB[M]);
        HornerB2<M - 1>::run(aA, aB, bA, bB, SA, SB);
    }
};
template <> struct HornerB2<-1> {
    __device__ static __forceinline__ void run(const uint64_t*, const uint64_t*,
                                               uint64_t, uint64_t, uint64_t&,
                                               uint64_t&) {}
};

__global__ void __launch_bounds__(128)
ipe_vec4_kernel(const float4* __restrict__ a, const float4* __restrict__ b,
                float4* __restrict__ out, int n4) {
    int i = blockIdx.x * blockDim.x + threadIdx.x;
    if (i >= n4) return;
    float4 av = a[i];
    float4 bv = b[i];

    uint64_t aPA = pk2(av.x, av.y);
    uint64_t aPB = pk2(av.z, av.w);
    uint64_t yA = mul2(aPA, aPA);          // y = a^2
    uint64_t yB = mul2(aPB, aPB);
    uint64_t y2A = mul2(yA, yA);
    uint64_t y2B = mul2(yB, yB);

    uint64_t accA[MM], accB[MM];
    InitStep2<0>::run(accA, accB);
    KStepEO2<1>::run(y2A, y2B, yA, y2A, yB, y2B, accA, accB);

    uint64_t bA = pk2(bv.x, bv.y);
    uint64_t bB = pk2(bv.z, bv.w);
    uint64_t SA = accA[RTOP], SB = accB[RTOP];
    HornerB2<RTOP - 1>::run(accA, accB, bA, bB, SA, SB);

    float s0, s1, s2, s3;
    upk2(s0, s1, SA);
    upk2(s2, s3, SB);

    float4 o;
    o.x = fmaf(__log2f(s0), LN2_F, CO0_F);
    o.y = fmaf(__log2f(s1), LN2_F, CO0_F);
    o.z = fmaf(__log2f(s2), LN2_F, CO0_F);
    o.w = fmaf(__log2f(s3), LN2_F, CO0_F);
    out[i] = o;
}

// ---- scalar fallback for the (empty in practice) tail ----

template <int M>
struct InitStepS {
    __device__ static __forceinline__ void run(float* acc) {
        if constexpr (rowLive(M)) acc[M] = toF(rcoefd(M));
        InitStepS<M + 1>::run(acc);
    }
};
template <> struct InitStepS<MM> { __device__ static __forceinline__ void run(float*) {} };

template <int M, int K>
struct MStepS {
    __device__ static __forceinline__ void run(float yk, float* acc) {
        if constexpr (keepT(M, K))
            acc[M] = fmaf(yk, toF(coefd(M, K) * rcoefd(M) / powc(4.0, K)), acc[M]);
        MStepS<M + 1, K>::run(yk, acc);
    }
};
template <int K> struct MStepS<MM, K> { __device__ static __forceinline__ void run(float, float*) {} };

template <int K>
struct KStepS {
    __device__ static __forceinline__ void run(float y2, float cur, float nxt,
                                               float* acc) {
        MStepS<0, K>::run(cur, acc);
        if constexpr (K + 1 <= KLIM)
            KStepS<K + 1>::run(y2, nxt, cur * y2, acc);
    }
};

template <int M>
struct HornerS {
    __device__ static __forceinline__ void run(const float* acc, float b,
                                               float& S) {
        S = fmaf(S, b, acc[M]);
        HornerS<M - 1>::run(acc, b, S);
    }
};
template <> struct HornerS<-1> {
    __device__ static __forceinline__ void run(const float*, float, float&) {}
};

__global__ void __launch_bounds__(128)
ipe_tail_kernel(const float* __restrict__ a, const float* __restrict__ b,
                float* __restrict__ out, int start, int n) {
    int i = start + blockIdx.x * blockDim.x + threadIdx.x;
    if (i >= n) return;
    float y = a[i] * a[i];
    float acc[MM];
    InitStepS<0>::run(acc);
    float y2 = y * y;
    KStepS<1>::run(y2, y, y2, acc);
    float S = acc[RTOP];
    HornerS<RTOP - 1>::run(acc, b[i], S);
    out[i] = fmaf(__log2f(S), LN2_F, CO0_F);
}

extern "C" void kernel_launch(void* const* d_in, const int* in_sizes, int n_in,
                              void* d_out, int out_size) {
    const float* a = (const float*)d_in[0];
    const float* b = (const float*)d_in[1];
    float* out = (float*)d_out;
    int n = in_sizes[0];
    int n4 = n / 4;
    if (n4 > 0) {
        int threads = 128;
        int blocks = (n4 + threads - 1) / threads;
        ipe_vec4_kernel<<<blocks, threads>>>((const float4*)a, (const float4*)b,
                                             (float4*)out, n4);
    }
    int rem = n - n4 * 4;
    if (rem > 0) {
        ipe_tail_kernel<<<1, 128>>>(a, b, out, n4 * 4, n);
    }
}

// round 17
// speedup vs baseline: 1.1020x; 1.0561x over previous
#include <cuda_runtime.h>
#include <cstdint>

// out = log( P0(y) + b*(P1(y) + b*P2(y)) ) + CO_0,   y = a*a
//   P_m(y) = sum_k D'[m,k] y^k,  D'[m,k] = C[m,k]*r_m/4^k
// All terms positive, D'[0,0]=1 so S >= 1: single log2 + FFMA, no exps.
// COMPILE-TIME pruning (verified rel_err ~3.9e-7 across rounds):
//   drop terms with D[m,k]*XMAX^k*BMAX^m < THRESH, XMAX=6.25, THRESH=1e-5
//   (pruning truncates only row tails -> Horner lists stay dense).
// R17: nested HORNER per row replaces power-ladder+accumulate: ~25% fewer
// packed ops, no acc[] array (lower regs). Shape = proven best (vec4/thread
// = 2 packed f32x2 lanes, 128-thread blocks, 1024 CTAs).

constexpr int MM = 8;
constexpr int KK = 17;

__host__ __device__ constexpr double coefd(int m, int k) {
    double c = 1.0;
    for (int j = 1; j <= k; ++j)
        c *= (3.5 + (double)j) /
             (((double)j - 0.5) * (2.0 * m + 4.0 + (double)j) * (double)j);
    return c;
}
__host__ __device__ constexpr double rcoefd(int m) {
    double r = 1.0;
    for (int j = 1; j <= m; ++j)
        r *= ((2.0 * j - 1.5) * (2.0 * j - 0.5)) /
             (4.0 * (2.0 * j + 3.0) * (2.0 * j + 4.0) * (double)j * (double)j);
    return r;
}
__host__ __device__ constexpr double powc(double b, int e) {
    double r = 1.0;
    for (int i = 0; i < e; ++i) r *= b;
    return r;
}

constexpr double XMAX = 6.25, BMAX = 0.95, THRESH = 1e-5;

__host__ __device__ constexpr bool keepT(int m, int k) {
    return coefd(m, k) * rcoefd(m) * powc(XMAX, k) * powc(BMAX, m) >= THRESH;
}
__host__ __device__ constexpr bool rowLive(int m) {
    for (int k = 0; k < KK; ++k)
        if (keepT(m, k)) return true;
    return false;
}
// highest live k for row m (Horner degree)
__host__ __device__ constexpr int rowKmax(int m) {
    int mk = 0;
    for (int k = 0; k < KK; ++k)
        if (keepT(m, k)) mk = k;
    return mk;
}
__host__ __device__ constexpr int maxLiveRow() {
    int r = 0;
    for (int m = 0; m < MM; ++m)
        if (rowLive(m)) r = m;
    return r;
}
constexpr int RTOP = maxLiveRow();

__host__ __device__ constexpr float toF(double v) {
    return (v < 1e-37 && v > -1e-37) ? 0.0f : (float)v;
}
// coefficient of y^k in row m (0 if pruned)
__host__ __device__ constexpr float rowCoef(int m, int k) {
    return keepT(m, k) ? toF(coefd(m, k) * rcoefd(m) / powc(4.0, k)) : 0.0f;
}

// CO_0 = lgamma(0.5) + lgamma(4.5) - lgamma(5)
#define CO0_F (-0.15195235f)
#define LN2_F (0.69314718f)

// ---- packed f32x2 primitives ----

__device__ __forceinline__ uint64_t pk2(float lo, float hi) {
    uint64_t r;
    asm("mov.b64 %0, {%1, %2};" : "=l"(r) : "f"(lo), "f"(hi));
    return r;
}
__device__ __forceinline__ void upk2(float& lo, float& hi, uint64_t v) {
    asm("mov.b64 {%0, %1}, %2;" : "=f"(lo), "=f"(hi) : "l"(v));
}
__device__ __forceinline__ uint64_t mul2(uint64_t a, uint64_t b) {
    uint64_t r;
    asm("mul.rn.f32x2 %0, %1, %2;" : "=l"(r) : "l"(a), "l"(b));
    return r;
}
__device__ __forceinline__ uint64_t fma2(uint64_t a, uint64_t b, uint64_t c) {
    uint64_t r;
    asm("fma.rn.f32x2 %0, %1, %2, %3;" : "=l"(r) : "l"(a), "l"(b), "l"(c));
    return r;
}

// ---- packed Horner in y for row M, two lanes, descending k ----

template <int M, int K>
struct RowH {
    __device__ static __forceinline__ void run(uint64_t yA, uint64_t yB,
                                               uint64_t& pA, uint64_t& pB) {
        constexpr float cv = rowCoef(M, K);
        uint64_t cc = pk2(cv, cv);
        pA = fma2(pA, yA, cc);
        pB = fma2(pB, yB, cc);
        if constexpr (K > 0) RowH<M, K - 1>::run(yA, yB, pA, pB);
    }
};

template <int M>
__device__ __forceinline__ void rowPoly(uint64_t yA, uint64_t yB,
                                        uint64_t& pA, uint64_t& pB) {
    constexpr int KM = rowKmax(M);
    constexpr float top = rowCoef(M, KM);
    pA = pk2(top, top);
    pB = pk2(top, top);
    if constexpr (KM > 0) RowH<M, KM - 1>::run(yA, yB, pA, pB);
}

// nested Horner in b over live rows (descending): S = P0 + b*(P1 + b*P2 ...)
template <int M>
struct OuterH {
    __device__ static __forceinline__ void run(uint64_t yA, uint64_t yB,
                                               uint64_t bA, uint64_t bB,
                                               uint64_t& SA, uint64_t& SB) {
        if constexpr (rowLive(M)) {
            uint64_t pA, pB;
            rowPoly<M>(yA, yB, pA, pB);
            if constexpr (M == RTOP) {
                SA = pA;
                SB = pB;
            } else {
                SA = fma2(SA, bA, pA);
                SB = fma2(SB, bB, pB);
            }
        }
        if constexpr (M > 0) OuterH<M - 1>::run(yA, yB, bA, bB, SA, SB);
    }
};

__global__ void __launch_bounds__(128)
ipe_vec4_kernel(const float4* __restrict__ a, const float4* __restrict__ b,
                float4* __restrict__ out, int n4) {
    int i = blockIdx.x * blockDim.x + threadIdx.x;
    if (i >= n4) return;
    float4 av = a[i];
    float4 bv = b[i];

    uint64_t aPA = pk2(av.x, av.y);
    uint64_t aPB = pk2(av.z, av.w);
    uint64_t yA = mul2(aPA, aPA);          // y = a^2
    uint64_t yB = mul2(aPB, aPB);
    uint64_t bA = pk2(bv.x, bv.y);
    uint64_t bB = pk2(bv.z, bv.w);

    uint64_t SA, SB;
    OuterH<RTOP>::run(yA, yB, bA, bB, SA, SB);

    float s0, s1, s2, s3;
    upk2(s0, s1, SA);
    upk2(s2, s3, SB);

    float4 o;
    o.x = fmaf(__log2f(s0), LN2_F, CO0_F);
    o.y = fmaf(__log2f(s1), LN2_F, CO0_F);
    o.z = fmaf(__log2f(s2), LN2_F, CO0_F);
    o.w = fmaf(__log2f(s3), LN2_F, CO0_F);
    out[i] = o;
}

// ---- scalar fallback for the (empty in practice) tail ----

template <int M, int K>
struct RowHS {
    __device__ static __forceinline__ void run(float y, float& p) {
        p = fmaf(p, y, rowCoef(M, K));
        if constexpr (K > 0) RowHS<M, K - 1>::run(y, p);
    }
};
template <int M>
__device__ __forceinline__ float rowPolyS(float y) {
    constexpr int KM = rowKmax(M);
    float p = rowCoef(M, KM);
    if constexpr (KM > 0) RowHS<M, KM - 1>::run(y, p);
    return p;
}
template <int M>
struct OuterHS {
    __device__ static __forceinline__ void run(float y, float b, float& S) {
        if constexpr (rowLive(M)) {
            float p = rowPolyS<M>(y);
            if constexpr (M == RTOP) S = p;
            else S = fmaf(S, b, p);
        }
        if constexpr (M > 0) OuterHS<M - 1>::run(y, b, S);
    }
};

__global__ void __launch_bounds__(128)
ipe_tail_kernel(const float* __restrict__ a, const float* __restrict__ b,
                float* __restrict__ out, int start, int n) {
    int i = start + blockIdx.x * blockDim.x + threadIdx.x;
    if (i >= n) return;
    float y = a[i] * a[i];
    float S;
    OuterHS<RTOP>::run(y, b[i], S);
    out[i] = fmaf(__log2f(S), LN2_F, CO0_F);
}

extern "C" void kernel_launch(void* const* d_in, const int* in_sizes, int n_in,
                              void* d_out, int out_size) {
    const float* a = (const float*)d_in[0];
    const float* b = (const float*)d_in[1];
    float* out = (float*)d_out;
    int n = in_sizes[0];
    int n4 = n / 4;
    if (n4 > 0) {
        int threads = 128;
        int blocks = (n4 + threads - 1) / threads;
        ipe_vec4_kernel<<<blocks, threads>>>((const float4*)a, (const float4*)b,
                                             (float4*)out, n4);
    }
    int rem = n - n4 * 4;
    if (rem > 0) {
        ipe_tail_kernel<<<1, 128>>>(a, b, out, n4 * 4, n);
    }
}